// round 1
// baseline (speedup 1.0000x reference)
#include <cuda_runtime.h>

#define NPIX 65536
#define NB   4
#define DD   256
#define FF   512

// ---------------- scratch (device globals; no runtime allocation) ----------
__device__ float  g_y  [NB * 128 * NPIX];   // after dw+bn+silu        (134 MB)
__device__ float  g_p  [NB * DD  * NPIX];   // residual stream         (268 MB)
__device__ float  g_z  [NB * DD  * NPIX];   // normalized              (268 MB)
__device__ float  g_a  [NB * DD  * NPIX];   // v -> a                  (268 MB)
__device__ float  g_h  [NB * FF  * NPIX];   // ffn hidden              (537 MB)
__device__ float  g_q  [NB * NPIX];
__device__ float  g_s  [NB * NPIX];
__device__ float  g_zs [NB * DD * 64];
__device__ float  g_ctx[NB * DD * 64];
__device__ double g_part[NB * 1024 * 2];
__device__ float  g_stat[NB * 2];           // mean, rstd per batch

// ---------------- depthwise 3x3 + bias + bn + silu --------------------------
__global__ void dw_silu(const float* __restrict__ x, const float* __restrict__ dww,
                        const float* __restrict__ dwb, const float* __restrict__ bg,
                        const float* __restrict__ bb, float* __restrict__ out) {
    size_t idx = (size_t)blockIdx.x * blockDim.x + threadIdx.x;
    int pos = (int)(idx & 65535);
    int h = pos >> 8, w = pos & 255;
    int c = (int)((idx >> 16) & 127);
    const float* xp = x + (idx - (size_t)pos);
    float wk[9];
#pragma unroll
    for (int i = 0; i < 9; i++) wk[i] = dww[c * 9 + i];
    float acc = 0.f;
#pragma unroll
    for (int kh = -1; kh <= 1; kh++) {
        int h2 = h + kh;
        if (h2 < 0 || h2 > 255) continue;
#pragma unroll
        for (int kw = -1; kw <= 1; kw++) {
            int w2 = w + kw;
            if (w2 < 0 || w2 > 255) continue;
            acc += xp[h2 * 256 + w2] * wk[(kh + 1) * 3 + (kw + 1)];
        }
    }
    acc += dwb[c];
    acc = acc * (bg[c] * rsqrtf(1.f + 1e-5f)) + bb[c];
    out[idx] = acc / (1.f + expf(-acc));
}

// ---------------- GN statistics (deterministic two-stage, fp64) ------------
__global__ void stats1(const float* __restrict__ p) {
    int b = blockIdx.y;
    const float* base = p + (size_t)b * DD * NPIX + (size_t)blockIdx.x * 16384;
    float s = 0.f, sq = 0.f;
    for (int i = threadIdx.x; i < 16384; i += 256) {
        float v = base[i];
        s += v; sq += v * v;
    }
    __shared__ double sh[256], sh2[256];
    sh[threadIdx.x] = (double)s; sh2[threadIdx.x] = (double)sq;
    __syncthreads();
    for (int st = 128; st > 0; st >>= 1) {
        if (threadIdx.x < st) {
            sh[threadIdx.x]  += sh[threadIdx.x + st];
            sh2[threadIdx.x] += sh2[threadIdx.x + st];
        }
        __syncthreads();
    }
    if (threadIdx.x == 0) {
        g_part[(b * 1024 + blockIdx.x) * 2]     = sh[0];
        g_part[(b * 1024 + blockIdx.x) * 2 + 1] = sh2[0];
    }
}

__global__ void stats2() {
    int b = blockIdx.x;
    double s = 0.0, sq = 0.0;
    for (int i = threadIdx.x; i < 1024; i += 256) {
        s  += g_part[(b * 1024 + i) * 2];
        sq += g_part[(b * 1024 + i) * 2 + 1];
    }
    __shared__ double sh[256], sh2[256];
    sh[threadIdx.x] = s; sh2[threadIdx.x] = sq;
    __syncthreads();
    for (int st = 128; st > 0; st >>= 1) {
        if (threadIdx.x < st) {
            sh[threadIdx.x]  += sh[threadIdx.x + st];
            sh2[threadIdx.x] += sh2[threadIdx.x + st];
        }
        __syncthreads();
    }
    if (threadIdx.x == 0) {
        double n   = (double)DD * (double)NPIX;
        double m   = sh[0] / n;
        double var = sh2[0] / n - m * m;
        g_stat[b * 2]     = (float)m;
        g_stat[b * 2 + 1] = (float)(1.0 / sqrt(var + 1e-5));
    }
}

__global__ void gn_apply(const float* __restrict__ p, const float* __restrict__ g,
                         const float* __restrict__ bb, float* __restrict__ z) {
    size_t idx = (size_t)blockIdx.x * 256 + threadIdx.x;
    int c = (int)((idx >> 16) & 255);
    int b = (int)(idx >> 24);
    float m = g_stat[b * 2], rs = g_stat[b * 2 + 1];
    z[idx] = (p[idx] - m) * rs * g[c] + bb[c];
}

// ---------------- q = Wq . z (per pixel dot over 256 channels) -------------
__global__ void q_kernel(const float* __restrict__ z, const float* __restrict__ wq,
                         const float* __restrict__ qb, float* __restrict__ qout) {
    int b = blockIdx.y;
    int pos = blockIdx.x * 256 + threadIdx.x;
    const float* zp = z + ((size_t)(b * DD) << 16) + pos;
    float acc = qb[0];
#pragma unroll 4
    for (int c = 0; c < DD; c++) acc += wq[c] * zp[(size_t)c << 16];
    qout[b * NPIX + pos] = acc;
}

// ---------------- softmax over each (b, h%8, w%8) group of 1024 ------------
__global__ void softmax_k(const float* __restrict__ qin, float* __restrict__ sout) {
    int b = blockIdx.y;
    int pg = blockIdx.x;               // 0..63
    int ph = pg >> 3, pw = pg & 7;
    const float* qb = qin + b * NPIX;
    float* sb = sout + b * NPIX;
    int t = threadIdx.x;
    float v[4]; int posA[4];
#pragma unroll
    for (int r = 0; r < 4; r++) {
        int e = t + 256 * r;
        int i = e >> 5, j = e & 31;
        int pos = (ph + 8 * i) * 256 + pw + 8 * j;
        posA[r] = pos;
        v[r] = qb[pos];
    }
    __shared__ float sh[256];
    float mx = fmaxf(fmaxf(v[0], v[1]), fmaxf(v[2], v[3]));
    sh[t] = mx; __syncthreads();
    for (int st = 128; st > 0; st >>= 1) {
        if (t < st) sh[t] = fmaxf(sh[t], sh[t + st]);
        __syncthreads();
    }
    mx = sh[0];
    __syncthreads();
    float e[4]; float loc = 0.f;
#pragma unroll
    for (int r = 0; r < 4; r++) { e[r] = expf(v[r] - mx); loc += e[r]; }
    sh[t] = loc; __syncthreads();
    for (int st = 128; st > 0; st >>= 1) {
        if (t < st) sh[t] += sh[t + st];
        __syncthreads();
    }
    float inv = 1.f / sh[0];
#pragma unroll
    for (int r = 0; r < 4; r++) sb[posA[r]] = e[r] * inv;
}

// ---------------- zs[b,c,p] = sum_n score * z  (p = (h%8)*8 + w%8) ---------
__global__ void zs_k(const float* __restrict__ z, const float* __restrict__ s,
                     float* __restrict__ zs) {
    int b = blockIdx.y, c = blockIdx.x;
    const float* zp = z + ((size_t)(b * DD + c) << 16);
    const float* sp = s + b * NPIX;
    int t = threadIdx.x;                 // thread t owns column w=t -> pw=t&7
    float acc[8] = {0, 0, 0, 0, 0, 0, 0, 0};
    for (int h = 0; h < 256; h++) {
        int pos = h * 256 + t;
        acc[h & 7] += zp[pos] * sp[pos];
    }
    __shared__ float sh[8][256];
#pragma unroll
    for (int ph = 0; ph < 8; ph++) sh[ph][t] = acc[ph];
    __syncthreads();
    if (t < 64) {
        int ph = t >> 3, pw = t & 7;
        float sum = 0.f;
        for (int k = 0; k < 32; k++) sum += sh[ph][pw + 8 * k];
        zs[((b * DD + c) << 6) + t] = sum;
    }
}

// ---------------- ctx = Wk @ zs + bk  (tiny GEMM) ---------------------------
__global__ void ctx_k(const float* __restrict__ wk, const float* __restrict__ bk,
                      const float* __restrict__ zs, float* __restrict__ ctx) {
    int b = blockIdx.y, d = blockIdx.x;
    int p = threadIdx.x;                 // 64
    float acc = bk[d];
    for (int c = 0; c < DD; c++)
        acc += wk[d * DD + c] * zs[((b * DD + c) << 6) + p];
    ctx[((b * DD + d) << 6) + p] = acc;
}

// ---------------- tiled SGEMM: C[b,M,NPIX] (+)= W[M,K] @ X[b,K,NPIX] --------
enum { EPI_BIAS = 0, EPI_SILU = 1, EPI_RELU_CTX = 2, EPI_ADD = 3, EPI_BN = 4 };

template <int EPI>
__global__ __launch_bounds__(256)
void gemm_k(const float* __restrict__ W, const float* __restrict__ X,
            const float* __restrict__ bias, float* __restrict__ C,
            int M, int K,
            const float* __restrict__ e0, const float* __restrict__ e1) {
    __shared__ float sW[8][128];
    __shared__ float sX[8][128];
    int b  = blockIdx.z;
    int m0 = blockIdx.y * 128;
    int n0 = blockIdx.x * 128;
    const float* Xb = X + (size_t)b * K * NPIX;
    float* Cb = C + (size_t)b * M * NPIX;
    int tid = threadIdx.x;
    int wr = tid >> 1, wc = (tid & 1) * 4;   // W tile load: row, k-offset
    int xr = tid >> 5, xc = (tid & 31) * 4;  // X tile load
    int tx = tid & 15, ty = tid >> 4;

    float acc[8][8];
#pragma unroll
    for (int i = 0; i < 8; i++)
#pragma unroll
        for (int j = 0; j < 8; j++) acc[i][j] = 0.f;

    for (int k0 = 0; k0 < K; k0 += 8) {
        float4 wv = *(const float4*)(W + (size_t)(m0 + wr) * K + k0 + wc);
        sW[wc + 0][wr] = wv.x; sW[wc + 1][wr] = wv.y;
        sW[wc + 2][wr] = wv.z; sW[wc + 3][wr] = wv.w;
        *(float4*)&sX[xr][xc] =
            *(const float4*)(Xb + (size_t)(k0 + xr) * NPIX + n0 + xc);
        __syncthreads();
#pragma unroll
        for (int kk = 0; kk < 8; kk++) {
            float a[8], bb[8];
            *(float4*)(a)     = *(float4*)&sW[kk][ty * 8];
            *(float4*)(a + 4) = *(float4*)&sW[kk][ty * 8 + 4];
            *(float4*)(bb)     = *(float4*)&sX[kk][tx * 8];
            *(float4*)(bb + 4) = *(float4*)&sX[kk][tx * 8 + 4];
#pragma unroll
            for (int i = 0; i < 8; i++)
#pragma unroll
                for (int j = 0; j < 8; j++) acc[i][j] += a[i] * bb[j];
        }
        __syncthreads();
    }

#pragma unroll
    for (int i = 0; i < 8; i++) {
        int m = m0 + ty * 8 + i;
        float bi = bias[m];
        size_t row = (size_t)m * NPIX;
#pragma unroll
        for (int j = 0; j < 8; j++) {
            int n = n0 + tx * 8 + j;
            float v = acc[i][j] + bi;
            if constexpr (EPI == EPI_SILU) {
                v = v / (1.f + expf(-v));
            } else if constexpr (EPI == EPI_RELU_CTX) {
                int g = ((n >> 8) & 7) * 8 + (n & 7);
                v = fmaxf(v, 0.f) * e0[(size_t)(b * DD + m) * 64 + g];
            } else if constexpr (EPI == EPI_ADD) {
                v += Cb[row + n];
            } else if constexpr (EPI == EPI_BN) {
                v = v * (e0[m] * rsqrtf(1.f + 1e-5f)) + e1[m];
            }
            Cb[row + n] = v;
        }
    }
}

// ---------------- driver -----------------------------------------------------
extern "C" void kernel_launch(void* const* d_in, const int* in_sizes, int n_in,
                              void* d_out, int out_size) {
    const float* x     = (const float*)d_in[0];
    const float* dww   = (const float*)d_in[1];
    const float* dwb   = (const float*)d_in[2];
    const float* bn1g  = (const float*)d_in[3];
    const float* bn1b  = (const float*)d_in[4];
    const float* pwinw = (const float*)d_in[5];
    const float* pwinb = (const float*)d_in[6];
    const float* gn1g  = (const float*)d_in[7];
    const float* gn1b  = (const float*)d_in[8];
    const float* qkvw  = (const float*)d_in[9];
    const float* qkvb  = (const float*)d_in[10];
    const float* outw  = (const float*)d_in[11];
    const float* outb  = (const float*)d_in[12];
    const float* gn2g  = (const float*)d_in[13];
    const float* gn2b  = (const float*)d_in[14];
    const float* ffn1w = (const float*)d_in[15];
    const float* ffn1b = (const float*)d_in[16];
    const float* ffn2w = (const float*)d_in[17];
    const float* ffn2b = (const float*)d_in[18];
    const float* gnfg  = (const float*)d_in[19];
    const float* gnfb  = (const float*)d_in[20];
    const float* projw = (const float*)d_in[21];
    const float* projb = (const float*)d_in[22];
    const float* bn2g  = (const float*)d_in[23];
    const float* bn2b  = (const float*)d_in[24];

    float *p_y, *p_p, *p_z, *p_a, *p_h, *p_q, *p_s, *p_zs, *p_ctx;
    cudaGetSymbolAddress((void**)&p_y,   g_y);
    cudaGetSymbolAddress((void**)&p_p,   g_p);
    cudaGetSymbolAddress((void**)&p_z,   g_z);
    cudaGetSymbolAddress((void**)&p_a,   g_a);
    cudaGetSymbolAddress((void**)&p_h,   g_h);
    cudaGetSymbolAddress((void**)&p_q,   g_q);
    cudaGetSymbolAddress((void**)&p_s,   g_s);
    cudaGetSymbolAddress((void**)&p_zs,  g_zs);
    cudaGetSymbolAddress((void**)&p_ctx, g_ctx);

    // 1) dw conv + bn + silu
    dw_silu<<<(NB * 128 * NPIX) / 256, 256>>>(x, dww, dwb, bn1g, bn1b, p_y);

    // 2) pw_in: p = W @ y + b   (M=256, K=128)
    gemm_k<EPI_BIAS><<<dim3(512, 2, NB), 256>>>(pwinw, p_y, pwinb, p_p,
                                                256, 128, nullptr, nullptr);

    for (int i = 0; i < 2; i++) {
        const float* qw = qkvw + (size_t)i * 513 * 256;
        const float* qb = qkvb + (size_t)i * 513;

        // GN1 + z
        stats1<<<dim3(1024, NB), 256>>>(p_p);
        stats2<<<NB, 256>>>();
        gn_apply<<<(NB * DD * NPIX) / 256, 256>>>(p_p, gn1g + i * 256, gn1b + i * 256, p_z);

        // attention (linear form)
        q_kernel<<<dim3(256, NB), 256>>>(p_z, qw, qb, p_q);
        softmax_k<<<dim3(64, NB), 256>>>(p_q, p_s);
        zs_k<<<dim3(256, NB), 256>>>(p_z, p_s, p_zs);
        ctx_k<<<dim3(256, NB), 64>>>(qw + 256, qb + 1, p_zs, p_ctx);

        // a = relu(Wv z + bv) * ctx ;  p += Wout a + bout
        gemm_k<EPI_RELU_CTX><<<dim3(512, 2, NB), 256>>>(qw + 257 * 256, p_z, qb + 257,
                                                        p_a, 256, 256, p_ctx, nullptr);
        gemm_k<EPI_ADD><<<dim3(512, 2, NB), 256>>>(outw + (size_t)i * 256 * 256, p_a,
                                                   outb + i * 256, p_p, 256, 256,
                                                   nullptr, nullptr);

        // GN2 + FFN
        stats1<<<dim3(1024, NB), 256>>>(p_p);
        stats2<<<NB, 256>>>();
        gn_apply<<<(NB * DD * NPIX) / 256, 256>>>(p_p, gn2g + i * 256, gn2b + i * 256, p_z);
        gemm_k<EPI_SILU><<<dim3(512, 4, NB), 256>>>(ffn1w + (size_t)i * 512 * 256, p_z,
                                                    ffn1b + i * 512, p_h, 512, 256,
                                                    nullptr, nullptr);
        gemm_k<EPI_ADD><<<dim3(512, 2, NB), 256>>>(ffn2w + (size_t)i * 256 * 512, p_h,
                                                   ffn2b + i * 256, p_p, 256, 512,
                                                   nullptr, nullptr);
    }

    // final GN + proj + bn2
    stats1<<<dim3(1024, NB), 256>>>(p_p);
    stats2<<<NB, 256>>>();
    gn_apply<<<(NB * DD * NPIX) / 256, 256>>>(p_p, gnfg, gnfb, p_z);
    gemm_k<EPI_BN><<<dim3(512, 1, NB), 256>>>(projw, p_z, projb, (float*)d_out,
                                              128, 256, bn2g, bn2b);
}

// round 2
// speedup vs baseline: 1.9891x; 1.9891x over previous
#include <cuda_runtime.h>
#include <cstdint>

#define NPIX 65536
#define NB   4
#define DD   256
#define FF   512

// ---------------- scratch (device globals; no runtime allocation) ----------
__device__ float  g_y  [NB * 128 * NPIX];   // after dw+bn+silu
__device__ float  g_p  [NB * DD  * NPIX];   // residual stream
__device__ float  g_a  [NB * DD  * NPIX];   // v -> a
__device__ float  g_h  [NB * FF  * NPIX];   // ffn hidden
__device__ float  g_q  [NB * NPIX];         // raw q (pre-scale)
__device__ float  g_s  [NB * NPIX];         // softmax scores
__device__ float  g_zs [NB * DD * 64];      // raw score-weighted sums of p
__device__ float  g_ctx[NB * DD * 64];
__device__ float  g_wt [851968];            // transposed tf32 weights
__device__ double g_acc[NB * 2];            // stats accumulators
__device__ float  g_stat[NB * 2];           // mean, rstd per batch

__device__ __forceinline__ float to_tf32(float v) {
    asm("cvt.rna.tf32.f32 %0, %0;" : "+f"(v));
    return v;
}

__device__ __forceinline__ void mma_tf32(float* c, const uint32_t* a, const uint32_t* b) {
    asm volatile(
        "mma.sync.aligned.m16n8k8.row.col.f32.tf32.tf32.f32 "
        "{%0,%1,%2,%3}, {%4,%5,%6,%7}, {%8,%9}, {%0,%1,%2,%3};"
        : "+f"(c[0]), "+f"(c[1]), "+f"(c[2]), "+f"(c[3])
        : "r"(a[0]), "r"(a[1]), "r"(a[2]), "r"(a[3]), "r"(b[0]), "r"(b[1]));
}

// ---------------- weight transpose + tf32 convert ---------------------------
__global__ void tpose(const float* __restrict__ W, float* __restrict__ WT, int M, int K) {
    int idx = blockIdx.x * 256 + threadIdx.x;
    if (idx >= M * K) return;
    int m = idx / K, k = idx - m * K;
    WT[k * M + m] = to_tf32(W[idx]);
}

__global__ void zero_acc() {
    if (threadIdx.x < NB * 2) g_acc[threadIdx.x] = 0.0;
}

__global__ void stats2() {
    int b = threadIdx.x;
    if (b >= NB) return;
    double n = (double)DD * (double)NPIX;
    double s = g_acc[b * 2], sq = g_acc[b * 2 + 1];
    double m = s / n;
    double var = sq / n - m * m;
    g_stat[b * 2]     = (float)m;
    g_stat[b * 2 + 1] = (float)(1.0 / sqrt(var + 1e-5));
    g_acc[b * 2] = 0.0;
    g_acc[b * 2 + 1] = 0.0;
}

// ---------------- depthwise 3x3 + bias + bn + silu --------------------------
__global__ void dw_silu(const float* __restrict__ x, const float* __restrict__ dww,
                        const float* __restrict__ dwb, const float* __restrict__ bg,
                        const float* __restrict__ bb, float* __restrict__ out) {
    size_t idx = (size_t)blockIdx.x * blockDim.x + threadIdx.x;
    int pos = (int)(idx & 65535);
    int h = pos >> 8, w = pos & 255;
    int c = (int)((idx >> 16) & 127);
    const float* xp = x + (idx - (size_t)pos);
    float wk[9];
#pragma unroll
    for (int i = 0; i < 9; i++) wk[i] = dww[c * 9 + i];
    float acc = 0.f;
#pragma unroll
    for (int kh = -1; kh <= 1; kh++) {
        int h2 = h + kh;
        if (h2 < 0 || h2 > 255) continue;
#pragma unroll
        for (int kw = -1; kw <= 1; kw++) {
            int w2 = w + kw;
            if (w2 < 0 || w2 > 255) continue;
            acc += xp[h2 * 256 + w2] * wk[(kh + 1) * 3 + (kw + 1)];
        }
    }
    acc += dwb[c];
    acc = acc * (bg[c] * rsqrtf(1.f + 1e-5f)) + bb[c];
    out[idx] = acc / (1.f + expf(-acc));
}

// ---------------- qraw[b,pos] = sum_c wq[c]*g1[c]*p[b,c,pos] ----------------
__global__ void q_kernel(const float* __restrict__ p, const float* __restrict__ wq,
                         const float* __restrict__ g1, float* __restrict__ qout) {
    int b = blockIdx.y;
    int pos = blockIdx.x * 256 + threadIdx.x;
    const float* pp = p + ((size_t)(b * DD) << 16) + pos;
    float acc = 0.f;
#pragma unroll 4
    for (int c = 0; c < DD; c++) acc += wq[c] * g1[c] * pp[(size_t)c << 16];
    qout[b * NPIX + pos] = acc;
}

// ---------------- softmax over each (b, h%8, w%8) group (scaled by rstd) ----
__global__ void softmax_k(const float* __restrict__ qin, float* __restrict__ sout) {
    int b = blockIdx.y;
    float rs = g_stat[b * 2 + 1];
    int pg = blockIdx.x;
    int ph = pg >> 3, pw = pg & 7;
    const float* qb = qin + b * NPIX;
    float* sb = sout + b * NPIX;
    int t = threadIdx.x;
    float v[4]; int posA[4];
#pragma unroll
    for (int r = 0; r < 4; r++) {
        int e = t + 256 * r;
        int i = e >> 5, j = e & 31;
        int pos = (ph + 8 * i) * 256 + pw + 8 * j;
        posA[r] = pos;
        v[r] = qb[pos] * rs;
    }
    __shared__ float sh[256];
    float mx = fmaxf(fmaxf(v[0], v[1]), fmaxf(v[2], v[3]));
    sh[t] = mx; __syncthreads();
    for (int st = 128; st > 0; st >>= 1) {
        if (t < st) sh[t] = fmaxf(sh[t], sh[t + st]);
        __syncthreads();
    }
    mx = sh[0];
    __syncthreads();
    float e[4]; float loc = 0.f;
#pragma unroll
    for (int r = 0; r < 4; r++) { e[r] = expf(v[r] - mx); loc += e[r]; }
    sh[t] = loc; __syncthreads();
    for (int st = 128; st > 0; st >>= 1) {
        if (t < st) sh[t] += sh[t + st];
        __syncthreads();
    }
    float inv = 1.f / sh[0];
#pragma unroll
    for (int r = 0; r < 4; r++) sb[posA[r]] = e[r] * inv;
}

// ---------------- zs_raw[b,c,g] = sum_n score * p ---------------------------
__global__ void zs_k(const float* __restrict__ p, const float* __restrict__ s,
                     float* __restrict__ zs) {
    int b = blockIdx.y, c = blockIdx.x;
    const float* zp = p + ((size_t)(b * DD + c) << 16);
    const float* sp = s + b * NPIX;
    int t = threadIdx.x;
    float acc[8] = {0, 0, 0, 0, 0, 0, 0, 0};
    for (int h = 0; h < 256; h++) {
        int pos = h * 256 + t;
        acc[h & 7] += zp[pos] * sp[pos];
    }
    __shared__ float sh[8][256];
#pragma unroll
    for (int ph = 0; ph < 8; ph++) sh[ph][t] = acc[ph];
    __syncthreads();
    if (t < 64) {
        int ph = t >> 3, pw = t & 7;
        float sum = 0.f;
        for (int k = 0; k < 32; k++) sum += sh[ph][pw + 8 * k];
        zs[((b * DD + c) << 6) + t] = sum;
    }
}

// ---------------- ctx = Wk @ gn1(zs) + bk -----------------------------------
__global__ void ctx_k(const float* __restrict__ wk, const float* __restrict__ bk,
                      const float* __restrict__ zs, float* __restrict__ ctx,
                      const float* __restrict__ g1, const float* __restrict__ b1) {
    int b = blockIdx.y, d = blockIdx.x;
    int pp = threadIdx.x;                 // 64
    float m = g_stat[b * 2], rs = g_stat[b * 2 + 1];
    float acc = bk[d];
    for (int c = 0; c < DD; c++) {
        float zv = (zs[((b * DD + c) << 6) + pp] - m) * rs * g1[c] + b1[c];
        acc += wk[d * DD + c] * zv;
    }
    ctx[((b * DD + d) << 6) + pp] = acc;
}

// ---------------- tf32 tensor-core GEMM -------------------------------------
// C[b, M, NPIX] (+)= WT^T @ gn?(X[b, K, NPIX]); WT is [K, M], pre-tf32.
enum { EPI_BIAS = 0, EPI_SILU = 1, EPI_RELU_CTX = 2, EPI_ADD = 3, EPI_BN = 4 };

template <int EPI, bool GNL, bool STATS>
__global__ __launch_bounds__(256, 2)
void gemm_tc(const float* __restrict__ WT, const float* __restrict__ X,
             const float* __restrict__ bias, float* __restrict__ C,
             int M, int K,
             const float* __restrict__ gnG, const float* __restrict__ gnB,
             const float* __restrict__ e0, const float* __restrict__ e1) {
    __shared__ float  sA[2][8][136];
    __shared__ float  sX[2][8][136];
    __shared__ double sred[16];

    const int b  = blockIdx.z;
    const int m0 = blockIdx.x * 128;
    const int n0 = blockIdx.y * 128;
    const float* Xb = X + (size_t)b * K * NPIX;
    float* Cb = C + (size_t)b * M * NPIX;
    const int tid = threadIdx.x, lane = tid & 31;
    const int wid = tid >> 5, wm = wid >> 2, wn = wid & 3;

    float gm = 0.f, grs = 1.f;
    if (GNL) { gm = g_stat[b * 2]; grs = g_stat[b * 2 + 1]; }

    const int lr = tid >> 5;            // load row within 8-row tile
    const int lc = (tid & 31) * 4;      // load col
    const float* aP = WT + (size_t)lr * M + m0 + lc;
    const float* xP = Xb + (size_t)lr * NPIX + n0 + lc;

    float acc[4][4][4];
#pragma unroll
    for (int i = 0; i < 4; i++)
#pragma unroll
        for (int j = 0; j < 4; j++)
#pragma unroll
            for (int r = 0; r < 4; r++) acc[i][j][r] = 0.f;

    const int KT = K >> 3;

    // prologue: tile 0
    float4 ra = *(const float4*)aP;
    float4 rx = *(const float4*)xP;
    if (GNL) {
        float sc = grs * gnG[lr];
        float sf = gnB[lr] - gm * sc;
        rx.x = rx.x * sc + sf; rx.y = rx.y * sc + sf;
        rx.z = rx.z * sc + sf; rx.w = rx.w * sc + sf;
    }
    rx.x = to_tf32(rx.x); rx.y = to_tf32(rx.y);
    rx.z = to_tf32(rx.z); rx.w = to_tf32(rx.w);
    *(float4*)&sA[0][lr][lc] = ra;
    *(float4*)&sX[0][lr][lc] = rx;
    __syncthreads();

    const int kr  = lane & 3;
    const int mtb = wm * 64 + (lane >> 2);
    const int ntb = wn * 32 + (lane >> 2);

    for (int kt = 0; kt < KT; kt++) {
        const int cur = kt & 1;
        if (kt + 1 < KT) {
            ra = *(const float4*)(aP + (size_t)(kt + 1) * 8 * M);
            rx = *(const float4*)(xP + (size_t)(kt + 1) * 8 * NPIX);
            if (GNL) {
                int c = (kt + 1) * 8 + lr;
                float sc = grs * gnG[c];
                float sf = gnB[c] - gm * sc;
                rx.x = rx.x * sc + sf; rx.y = rx.y * sc + sf;
                rx.z = rx.z * sc + sf; rx.w = rx.w * sc + sf;
            }
            rx.x = to_tf32(rx.x); rx.y = to_tf32(rx.y);
            rx.z = to_tf32(rx.z); rx.w = to_tf32(rx.w);
        }
        // compute on buffer `cur`
        uint32_t bf[4][2];
#pragma unroll
        for (int nt = 0; nt < 4; nt++) {
            bf[nt][0] = __float_as_uint(sX[cur][kr]    [ntb + nt * 8]);
            bf[nt][1] = __float_as_uint(sX[cur][kr + 4][ntb + nt * 8]);
        }
#pragma unroll
        for (int mt = 0; mt < 4; mt++) {
            uint32_t af[4];
            af[0] = __float_as_uint(sA[cur][kr]    [mtb + mt * 16]);
            af[1] = __float_as_uint(sA[cur][kr]    [mtb + mt * 16 + 8]);
            af[2] = __float_as_uint(sA[cur][kr + 4][mtb + mt * 16]);
            af[3] = __float_as_uint(sA[cur][kr + 4][mtb + mt * 16 + 8]);
#pragma unroll
            for (int nt = 0; nt < 4; nt++) mma_tf32(acc[mt][nt], af, bf[nt]);
        }
        if (kt + 1 < KT) {
            const int nxt = (kt + 1) & 1;
            *(float4*)&sA[nxt][lr][lc] = ra;
            *(float4*)&sX[nxt][lr][lc] = rx;
        }
        __syncthreads();
    }

    // ---------------- epilogue ----------------
    float lsum = 0.f, lsq = 0.f;
#pragma unroll
    for (int mt = 0; mt < 4; mt++) {
        int mrow = m0 + wm * 64 + mt * 16 + (lane >> 2);
        float bi0 = bias[mrow], bi1 = bias[mrow + 8];
        size_t r0 = (size_t)mrow * NPIX;
        size_t r1 = r0 + (size_t)8 * NPIX;
#pragma unroll
        for (int nt = 0; nt < 4; nt++) {
            int n = n0 + wn * 32 + nt * 8 + (lane & 3) * 2;
            float v00 = acc[mt][nt][0] + bi0;
            float v01 = acc[mt][nt][1] + bi0;
            float v10 = acc[mt][nt][2] + bi1;
            float v11 = acc[mt][nt][3] + bi1;
            if constexpr (EPI == EPI_SILU) {
                v00 = v00 / (1.f + expf(-v00));
                v01 = v01 / (1.f + expf(-v01));
                v10 = v10 / (1.f + expf(-v10));
                v11 = v11 / (1.f + expf(-v11));
            } else if constexpr (EPI == EPI_RELU_CTX) {
                int ga = ((n >> 8) & 7) * 8 + (n & 7);
                int gb2 = ((n >> 8) & 7) * 8 + ((n + 1) & 7);
                const float* cb = e0 + (size_t)b * DD * 64;
                v00 = fmaxf(v00, 0.f) * cb[mrow * 64 + ga];
                v01 = fmaxf(v01, 0.f) * cb[mrow * 64 + gb2];
                v10 = fmaxf(v10, 0.f) * cb[(mrow + 8) * 64 + ga];
                v11 = fmaxf(v11, 0.f) * cb[(mrow + 8) * 64 + gb2];
            } else if constexpr (EPI == EPI_ADD) {
                float2 o0 = *(const float2*)&Cb[r0 + n];
                float2 o1 = *(const float2*)&Cb[r1 + n];
                v00 += o0.x; v01 += o0.y; v10 += o1.x; v11 += o1.y;
            } else if constexpr (EPI == EPI_BN) {
                float rq = rsqrtf(1.f + 1e-5f);
                float s0 = e0[mrow] * rq,     f0 = e1[mrow];
                float s1 = e0[mrow + 8] * rq, f1 = e1[mrow + 8];
                v00 = v00 * s0 + f0; v01 = v01 * s0 + f0;
                v10 = v10 * s1 + f1; v11 = v11 * s1 + f1;
            }
            *(float2*)&Cb[r0 + n] = make_float2(v00, v01);
            *(float2*)&Cb[r1 + n] = make_float2(v10, v11);
            if (STATS) {
                lsum += v00 + v01 + v10 + v11;
                lsq  += v00 * v00 + v01 * v01 + v10 * v10 + v11 * v11;
            }
        }
    }
    if (STATS) {
#pragma unroll
        for (int o = 16; o; o >>= 1) {
            lsum += __shfl_xor_sync(0xffffffffu, lsum, o);
            lsq  += __shfl_xor_sync(0xffffffffu, lsq,  o);
        }
        if (lane == 0) { sred[wid] = (double)lsum; sred[8 + wid] = (double)lsq; }
        __syncthreads();
        if (tid == 0) {
            double S = 0, Q = 0;
#pragma unroll
            for (int i = 0; i < 8; i++) { S += sred[i]; Q += sred[8 + i]; }
            atomicAdd(&g_acc[b * 2], S);
            atomicAdd(&g_acc[b * 2 + 1], Q);
        }
    }
}

// ---------------- driver -----------------------------------------------------
extern "C" void kernel_launch(void* const* d_in, const int* in_sizes, int n_in,
                              void* d_out, int out_size) {
    const float* x     = (const float*)d_in[0];
    const float* dww   = (const float*)d_in[1];
    const float* dwb   = (const float*)d_in[2];
    const float* bn1g  = (const float*)d_in[3];
    const float* bn1b  = (const float*)d_in[4];
    const float* pwinw = (const float*)d_in[5];
    const float* pwinb = (const float*)d_in[6];
    const float* gn1g  = (const float*)d_in[7];
    const float* gn1b  = (const float*)d_in[8];
    const float* qkvw  = (const float*)d_in[9];
    const float* qkvb  = (const float*)d_in[10];
    const float* outw  = (const float*)d_in[11];
    const float* outb  = (const float*)d_in[12];
    const float* gn2g  = (const float*)d_in[13];
    const float* gn2b  = (const float*)d_in[14];
    const float* ffn1w = (const float*)d_in[15];
    const float* ffn1b = (const float*)d_in[16];
    const float* ffn2w = (const float*)d_in[17];
    const float* ffn2b = (const float*)d_in[18];
    const float* gnfg  = (const float*)d_in[19];
    const float* gnfb  = (const float*)d_in[20];
    const float* projw = (const float*)d_in[21];
    const float* projb = (const float*)d_in[22];
    const float* bn2g  = (const float*)d_in[23];
    const float* bn2b  = (const float*)d_in[24];

    float *p_y, *p_p, *p_a, *p_h, *p_q, *p_s, *p_zs, *p_ctx, *p_wt;
    cudaGetSymbolAddress((void**)&p_y,   g_y);
    cudaGetSymbolAddress((void**)&p_p,   g_p);
    cudaGetSymbolAddress((void**)&p_a,   g_a);
    cudaGetSymbolAddress((void**)&p_h,   g_h);
    cudaGetSymbolAddress((void**)&p_q,   g_q);
    cudaGetSymbolAddress((void**)&p_s,   g_s);
    cudaGetSymbolAddress((void**)&p_zs,  g_zs);
    cudaGetSymbolAddress((void**)&p_ctx, g_ctx);
    cudaGetSymbolAddress((void**)&p_wt,  g_wt);

    // weight-transpose offsets
    const int OFF_PWIN = 0;
    const int OFF_V[2]   = {32768, 425984};
    const int OFF_OUT[2] = {98304, 491520};
    const int OFF_F1[2]  = {163840, 557056};
    const int OFF_F2[2]  = {294912, 688128};
    const int OFF_PROJ   = 819200;

    zero_acc<<<1, 32>>>();
    tpose<<<128, 256>>>(pwinw, p_wt + OFF_PWIN, 256, 128);
    for (int i = 0; i < 2; i++) {
        tpose<<<256, 256>>>(qkvw + (size_t)i * 513 * 256 + 257 * 256, p_wt + OFF_V[i], 256, 256);
        tpose<<<256, 256>>>(outw + (size_t)i * 65536,  p_wt + OFF_OUT[i], 256, 256);
        tpose<<<512, 256>>>(ffn1w + (size_t)i * 131072, p_wt + OFF_F1[i], 512, 256);
        tpose<<<512, 256>>>(ffn2w + (size_t)i * 131072, p_wt + OFF_F2[i], 256, 512);
    }
    tpose<<<128, 256>>>(projw, p_wt + OFF_PROJ, 128, 256);

    // 1) dw conv + bn + silu
    dw_silu<<<(NB * 128 * NPIX) / 256, 256>>>(x, dww, dwb, bn1g, bn1b, p_y);

    // 2) pw_in: p = W @ y + b, with GN1 stats fused into epilogue
    gemm_tc<EPI_BIAS, false, true><<<dim3(2, 512, NB), 256>>>(
        p_wt + OFF_PWIN, p_y, pwinb, p_p, 256, 128, nullptr, nullptr, nullptr, nullptr);

    for (int i = 0; i < 2; i++) {
        const float* qw = qkvw + (size_t)i * 513 * 256;
        const float* qb = qkvb + (size_t)i * 513;
        const float* g1 = gn1g + i * 256;
        const float* b1 = gn1b + i * 256;
        const float* g2 = gn2g + i * 256;
        const float* b2 = gn2b + i * 256;

        stats2<<<1, 32>>>();  // finalize GN1 stats

        // attention (linear form, GN folded)
        q_kernel<<<dim3(256, NB), 256>>>(p_p, qw, g1, p_q);
        softmax_k<<<dim3(64, NB), 256>>>(p_q, p_s);
        zs_k<<<dim3(256, NB), 256>>>(p_p, p_s, p_zs);
        ctx_k<<<dim3(256, NB), 64>>>(qw + 256, qb + 1, p_zs, p_ctx, g1, b1);

        // a = relu(Wv gn1(p) + bv) * ctx
        gemm_tc<EPI_RELU_CTX, true, false><<<dim3(2, 512, NB), 256>>>(
            p_wt + OFF_V[i], p_p, qb + 257, p_a, 256, 256, g1, b1, p_ctx, nullptr);
        // p += Wout a + bout ; GN2 stats fused
        gemm_tc<EPI_ADD, false, true><<<dim3(2, 512, NB), 256>>>(
            p_wt + OFF_OUT[i], p_a, outb + i * 256, p_p, 256, 256,
            nullptr, nullptr, nullptr, nullptr);

        stats2<<<1, 32>>>();  // finalize GN2 stats

        // h = silu(W1 gn2(p) + b1)
        gemm_tc<EPI_SILU, true, false><<<dim3(4, 512, NB), 256>>>(
            p_wt + OFF_F1[i], p_p, ffn1b + i * 512, p_h, 512, 256, g2, b2, nullptr, nullptr);
        // p += W2 h + b2 ; next-GN stats fused
        gemm_tc<EPI_ADD, false, true><<<dim3(2, 512, NB), 256>>>(
            p_wt + OFF_F2[i], p_h, ffn2b + i * 256, p_p, 256, 512,
            nullptr, nullptr, nullptr, nullptr);
    }

    stats2<<<1, 32>>>();  // finalize final-GN stats

    // out = bn2(proj(gnf(p)))
    gemm_tc<EPI_BN, true, false><<<dim3(1, 512, NB), 256>>>(
        p_wt + OFF_PROJ, p_p, projb, (float*)d_out, 128, 256, gnfg, gnfb, bn2g, bn2b);
}

// round 3
// speedup vs baseline: 3.2146x; 1.6161x over previous
#include <cuda_runtime.h>
#include <cstdint>

#define NPIX 65536
#define NB   4
#define DD   256
#define FF   512

// ---------------- scratch (device globals; no runtime allocation) ----------
__device__ float  g_y  [NB * 128 * NPIX];   // after dw+bn+silu
__device__ float  g_p  [NB * DD  * NPIX];   // residual stream
__device__ float  g_a  [NB * DD  * NPIX];   // v -> a
__device__ float  g_h  [NB * FF  * NPIX];   // ffn hidden
__device__ float  g_q  [NB * NPIX];         // raw q (pre-scale)
__device__ float  g_s  [NB * NPIX];         // softmax scores
__device__ float  g_zs [NB * DD * 64];      // raw score-weighted sums of p
__device__ float  g_ctx[NB * DD * 64];
__device__ float  g_wt [851968];            // transposed tf32 weights
__device__ double g_acc[NB * 2];            // stats accumulators
__device__ float  g_stat[NB * 2];           // mean, rstd per batch

__device__ __forceinline__ float to_tf32(float v) {
    asm("cvt.rna.tf32.f32 %0, %0;" : "+f"(v));
    return v;
}

__device__ __forceinline__ void mma_tf32(float* c, const uint32_t* a, const uint32_t* b) {
    asm volatile(
        "mma.sync.aligned.m16n8k8.row.col.f32.tf32.tf32.f32 "
        "{%0,%1,%2,%3}, {%4,%5,%6,%7}, {%8,%9}, {%0,%1,%2,%3};"
        : "+f"(c[0]), "+f"(c[1]), "+f"(c[2]), "+f"(c[3])
        : "r"(a[0]), "r"(a[1]), "r"(a[2]), "r"(a[3]), "r"(b[0]), "r"(b[1]));
}

__device__ __forceinline__ void cp_async16(void* dst, const void* src) {
    uint32_t s = (uint32_t)__cvta_generic_to_shared(dst);
    asm volatile("cp.async.cg.shared.global [%0], [%1], 16;" :: "r"(s), "l"(src));
}
__device__ __forceinline__ void cp_commit() {
    asm volatile("cp.async.commit_group;");
}
template <int N>
__device__ __forceinline__ void cp_wait() {
    asm volatile("cp.async.wait_group %0;" :: "n"(N));
}

// ---------------- weight transpose + tf32 convert ---------------------------
__global__ void tpose(const float* __restrict__ W, float* __restrict__ WT, int M, int K) {
    int idx = blockIdx.x * 256 + threadIdx.x;
    if (idx >= M * K) return;
    int m = idx / K, k = idx - m * K;
    WT[k * M + m] = to_tf32(W[idx]);
}

__global__ void zero_acc() {
    if (threadIdx.x < NB * 2) g_acc[threadIdx.x] = 0.0;
}

__global__ void stats2() {
    int b = threadIdx.x;
    if (b >= NB) return;
    double n = (double)DD * (double)NPIX;
    double s = g_acc[b * 2], sq = g_acc[b * 2 + 1];
    double m = s / n;
    double var = sq / n - m * m;
    g_stat[b * 2]     = (float)m;
    g_stat[b * 2 + 1] = (float)(1.0 / sqrt(var + 1e-5));
    g_acc[b * 2] = 0.0;
    g_acc[b * 2 + 1] = 0.0;
}

// ---------------- depthwise 3x3 + bias + bn + silu --------------------------
__global__ void dw_silu(const float* __restrict__ x, const float* __restrict__ dww,
                        const float* __restrict__ dwb, const float* __restrict__ bg,
                        const float* __restrict__ bb, float* __restrict__ out) {
    size_t idx = (size_t)blockIdx.x * blockDim.x + threadIdx.x;
    int pos = (int)(idx & 65535);
    int h = pos >> 8, w = pos & 255;
    int c = (int)((idx >> 16) & 127);
    const float* xp = x + (idx - (size_t)pos);
    float wk[9];
#pragma unroll
    for (int i = 0; i < 9; i++) wk[i] = dww[c * 9 + i];
    float acc = 0.f;
#pragma unroll
    for (int kh = -1; kh <= 1; kh++) {
        int h2 = h + kh;
        if (h2 < 0 || h2 > 255) continue;
#pragma unroll
        for (int kw = -1; kw <= 1; kw++) {
            int w2 = w + kw;
            if (w2 < 0 || w2 > 255) continue;
            acc += xp[h2 * 256 + w2] * wk[(kh + 1) * 3 + (kw + 1)];
        }
    }
    acc += dwb[c];
    acc = acc * (bg[c] * rsqrtf(1.f + 1e-5f)) + bb[c];
    out[idx] = acc / (1.f + expf(-acc));
}

// ---------------- qraw[b,pos] = sum_c wq[c]*g1[c]*p[b,c,pos] ----------------
__global__ void q_kernel(const float* __restrict__ p, const float* __restrict__ wq,
                         const float* __restrict__ g1, float* __restrict__ qout) {
    int b = blockIdx.y;
    int pos = blockIdx.x * 256 + threadIdx.x;
    const float* pp = p + ((size_t)(b * DD) << 16) + pos;
    float acc = 0.f;
#pragma unroll 4
    for (int c = 0; c < DD; c++) acc += wq[c] * g1[c] * pp[(size_t)c << 16];
    qout[b * NPIX + pos] = acc;
}

// ---------------- softmax over each (b, h%8, w%8) group (scaled by rstd) ----
__global__ void softmax_k(const float* __restrict__ qin, float* __restrict__ sout) {
    int b = blockIdx.y;
    float rs = g_stat[b * 2 + 1];
    int pg = blockIdx.x;
    int ph = pg >> 3, pw = pg & 7;
    const float* qb = qin + b * NPIX;
    float* sb = sout + b * NPIX;
    int t = threadIdx.x;
    float v[4]; int posA[4];
#pragma unroll
    for (int r = 0; r < 4; r++) {
        int e = t + 256 * r;
        int i = e >> 5, j = e & 31;
        int pos = (ph + 8 * i) * 256 + pw + 8 * j;
        posA[r] = pos;
        v[r] = qb[pos] * rs;
    }
    __shared__ float sh[256];
    float mx = fmaxf(fmaxf(v[0], v[1]), fmaxf(v[2], v[3]));
    sh[t] = mx; __syncthreads();
    for (int st = 128; st > 0; st >>= 1) {
        if (t < st) sh[t] = fmaxf(sh[t], sh[t + st]);
        __syncthreads();
    }
    mx = sh[0];
    __syncthreads();
    float e[4]; float loc = 0.f;
#pragma unroll
    for (int r = 0; r < 4; r++) { e[r] = expf(v[r] - mx); loc += e[r]; }
    sh[t] = loc; __syncthreads();
    for (int st = 128; st > 0; st >>= 1) {
        if (t < st) sh[t] += sh[t + st];
        __syncthreads();
    }
    float inv = 1.f / sh[0];
#pragma unroll
    for (int r = 0; r < 4; r++) sb[posA[r]] = e[r] * inv;
}

// ---------------- zs_raw[b,c,g] = sum_n score * p ---------------------------
__global__ void zs_k(const float* __restrict__ p, const float* __restrict__ s,
                     float* __restrict__ zs) {
    int b = blockIdx.y, c = blockIdx.x;
    const float* zp = p + ((size_t)(b * DD + c) << 16);
    const float* sp = s + b * NPIX;
    int t = threadIdx.x;
    float acc[8] = {0, 0, 0, 0, 0, 0, 0, 0};
    for (int h = 0; h < 256; h++) {
        int pos = h * 256 + t;
        acc[h & 7] += zp[pos] * sp[pos];
    }
    __shared__ float sh[8][256];
#pragma unroll
    for (int ph = 0; ph < 8; ph++) sh[ph][t] = acc[ph];
    __syncthreads();
    if (t < 64) {
        int ph = t >> 3, pw = t & 7;
        float sum = 0.f;
        for (int k = 0; k < 32; k++) sum += sh[ph][pw + 8 * k];
        zs[((b * DD + c) << 6) + t] = sum;
    }
}

// ---------------- ctx = Wk @ gn1(zs) + bk -----------------------------------
__global__ void ctx_k(const float* __restrict__ wk, const float* __restrict__ bk,
                      const float* __restrict__ zs, float* __restrict__ ctx,
                      const float* __restrict__ g1, const float* __restrict__ b1) {
    int b = blockIdx.y, d = blockIdx.x;
    int pp = threadIdx.x;                 // 64
    float m = g_stat[b * 2], rs = g_stat[b * 2 + 1];
    float acc = bk[d];
    for (int c = 0; c < DD; c++) {
        float zv = (zs[((b * DD + c) << 6) + pp] - m) * rs * g1[c] + b1[c];
        acc += wk[d * DD + c] * zv;
    }
    ctx[((b * DD + d) << 6) + pp] = acc;
}

// ---------------- tf32 tensor-core GEMM, cp.async pipelined -----------------
// C[b, M, NPIX] (+)= WT^T @ gn?(X[b, K, NPIX]); WT is [K, M], pre-tf32.
enum { EPI_BIAS = 0, EPI_SILU = 1, EPI_RELU_CTX = 2, EPI_ADD = 3, EPI_BN = 4 };

#define BK 16

template <int EPI, bool GNL, bool STATS>
__global__ __launch_bounds__(256, 2)
void gemm_tc(const float* __restrict__ WT, const float* __restrict__ X,
             const float* __restrict__ bias, float* __restrict__ C,
             int M, int K,
             const float* __restrict__ gnG, const float* __restrict__ gnB,
             const float* __restrict__ e0, const float* __restrict__ e1) {
    __shared__ float  sA[2][BK][136];
    __shared__ float  sX[2][BK][136];
    __shared__ float  sSC[512], sSF[512];
    __shared__ double sred[16];

    const int b  = blockIdx.z;
    const int m0 = blockIdx.x * 128;
    const int n0 = blockIdx.y * 128;
    const float* Xb = X + (size_t)b * K * NPIX;
    float* Cb = C + (size_t)b * M * NPIX;
    const int tid = threadIdx.x, lane = tid & 31;
    const int wid = tid >> 5, wm = wid >> 2, wn = wid & 3;

    // GN per-channel affine table (applied on B fragments post-LDS; numerics
    // identical to applying at load time: same fp32 ops, then cvt.rna.tf32).
    if (GNL) {
        float gm = g_stat[b * 2], grs = g_stat[b * 2 + 1];
        for (int c = tid; c < K; c += 256) {
            float sc = grs * gnG[c];
            sSC[c] = sc;
            sSF[c] = gnB[c] - gm * sc;
        }
        __syncthreads();
    }

    // cp.async copy mapping: 512 16B-chunks per BK x 128 tile; 2 chunks/thread
    const int ck0 = tid, ck1 = tid + 256;
    const int k0r = ck0 >> 5, k0c = (ck0 & 31) * 4;
    const int k1r = ck1 >> 5, k1c = (ck1 & 31) * 4;

    const float* aB = WT + m0;
    const float* xB = Xb + n0;

    float acc[4][4][4];
#pragma unroll
    for (int i = 0; i < 4; i++)
#pragma unroll
        for (int j = 0; j < 4; j++)
#pragma unroll
            for (int r = 0; r < 4; r++) acc[i][j][r] = 0.f;

    const int KT = K / BK;

    // prologue: tile 0 in flight
    cp_async16(&sA[0][k0r][k0c], aB + (size_t)k0r * M + k0c);
    cp_async16(&sA[0][k1r][k1c], aB + (size_t)k1r * M + k1c);
    cp_async16(&sX[0][k0r][k0c], xB + (size_t)k0r * NPIX + k0c);
    cp_async16(&sX[0][k1r][k1c], xB + (size_t)k1r * NPIX + k1c);
    cp_commit();

    const int kr  = lane & 3;
    const int mtb = wm * 64 + (lane >> 2);
    const int ntb = wn * 32 + (lane >> 2);

    for (int kt = 0; kt < KT; kt++) {
        const int cur = kt & 1;
        if (kt + 1 < KT) {
            const int nxt = cur ^ 1;
            const float* aN = aB + (size_t)(kt + 1) * BK * M;
            const float* xN = xB + (size_t)(kt + 1) * BK * NPIX;
            cp_async16(&sA[nxt][k0r][k0c], aN + (size_t)k0r * M + k0c);
            cp_async16(&sA[nxt][k1r][k1c], aN + (size_t)k1r * M + k1c);
            cp_async16(&sX[nxt][k0r][k0c], xN + (size_t)k0r * NPIX + k0c);
            cp_async16(&sX[nxt][k1r][k1c], xN + (size_t)k1r * NPIX + k1c);
            cp_commit();
            cp_wait<1>();
        } else {
            cp_wait<0>();
        }
        __syncthreads();

#pragma unroll
        for (int kh = 0; kh < 2; kh++) {
            const int kk = kh * 8;
            const int r0 = kk + kr, r1 = kk + kr + 4;
            uint32_t bf[4][2];
#pragma unroll
            for (int nt = 0; nt < 4; nt++) {
                float x0 = sX[cur][r0][ntb + nt * 8];
                float x1 = sX[cur][r1][ntb + nt * 8];
                if (GNL) {
                    int c0 = kt * BK + r0, c1 = kt * BK + r1;
                    x0 = x0 * sSC[c0] + sSF[c0];
                    x1 = x1 * sSC[c1] + sSF[c1];
                }
                bf[nt][0] = __float_as_uint(to_tf32(x0));
                bf[nt][1] = __float_as_uint(to_tf32(x1));
            }
#pragma unroll
            for (int mt = 0; mt < 4; mt++) {
                uint32_t af[4];
                af[0] = __float_as_uint(sA[cur][r0][mtb + mt * 16]);
                af[1] = __float_as_uint(sA[cur][r0][mtb + mt * 16 + 8]);
                af[2] = __float_as_uint(sA[cur][r1][mtb + mt * 16]);
                af[3] = __float_as_uint(sA[cur][r1][mtb + mt * 16 + 8]);
#pragma unroll
                for (int nt = 0; nt < 4; nt++) mma_tf32(acc[mt][nt], af, bf[nt]);
            }
        }
        __syncthreads();
    }

    // ---------------- epilogue ----------------
    float lsum = 0.f, lsq = 0.f;
#pragma unroll
    for (int mt = 0; mt < 4; mt++) {
        int mrow = m0 + wm * 64 + mt * 16 + (lane >> 2);
        float bi0 = bias[mrow], bi1 = bias[mrow + 8];
        size_t r0 = (size_t)mrow * NPIX;
        size_t r1 = r0 + (size_t)8 * NPIX;
#pragma unroll
        for (int nt = 0; nt < 4; nt++) {
            int n = n0 + wn * 32 + nt * 8 + (lane & 3) * 2;
            float v00 = acc[mt][nt][0] + bi0;
            float v01 = acc[mt][nt][1] + bi0;
            float v10 = acc[mt][nt][2] + bi1;
            float v11 = acc[mt][nt][3] + bi1;
            if constexpr (EPI == EPI_SILU) {
                v00 = v00 / (1.f + expf(-v00));
                v01 = v01 / (1.f + expf(-v01));
                v10 = v10 / (1.f + expf(-v10));
                v11 = v11 / (1.f + expf(-v11));
            } else if constexpr (EPI == EPI_RELU_CTX) {
                int ga = ((n >> 8) & 7) * 8 + (n & 7);
                int gb2 = ((n >> 8) & 7) * 8 + ((n + 1) & 7);
                const float* cb = e0 + (size_t)b * DD * 64;
                v00 = fmaxf(v00, 0.f) * cb[mrow * 64 + ga];
                v01 = fmaxf(v01, 0.f) * cb[mrow * 64 + gb2];
                v10 = fmaxf(v10, 0.f) * cb[(mrow + 8) * 64 + ga];
                v11 = fmaxf(v11, 0.f) * cb[(mrow + 8) * 64 + gb2];
            } else if constexpr (EPI == EPI_ADD) {
                float2 o0 = *(const float2*)&Cb[r0 + n];
                float2 o1 = *(const float2*)&Cb[r1 + n];
                v00 += o0.x; v01 += o0.y; v10 += o1.x; v11 += o1.y;
            } else if constexpr (EPI == EPI_BN) {
                float rq = rsqrtf(1.f + 1e-5f);
                float s0 = e0[mrow] * rq,     f0 = e1[mrow];
                float s1 = e0[mrow + 8] * rq, f1 = e1[mrow + 8];
                v00 = v00 * s0 + f0; v01 = v01 * s0 + f0;
                v10 = v10 * s1 + f1; v11 = v11 * s1 + f1;
            }
            *(float2*)&Cb[r0 + n] = make_float2(v00, v01);
            *(float2*)&Cb[r1 + n] = make_float2(v10, v11);
            if (STATS) {
                lsum += v00 + v01 + v10 + v11;
                lsq  += v00 * v00 + v01 * v01 + v10 * v10 + v11 * v11;
            }
        }
    }
    if (STATS) {
#pragma unroll
        for (int o = 16; o; o >>= 1) {
            lsum += __shfl_xor_sync(0xffffffffu, lsum, o);
            lsq  += __shfl_xor_sync(0xffffffffu, lsq,  o);
        }
        if (lane == 0) { sred[wid] = (double)lsum; sred[8 + wid] = (double)lsq; }
        __syncthreads();
        if (tid == 0) {
            double S = 0, Q = 0;
#pragma unroll
            for (int i = 0; i < 8; i++) { S += sred[i]; Q += sred[8 + i]; }
            atomicAdd(&g_acc[b * 2], S);
            atomicAdd(&g_acc[b * 2 + 1], Q);
        }
    }
}

// ---------------- driver -----------------------------------------------------
extern "C" void kernel_launch(void* const* d_in, const int* in_sizes, int n_in,
                              void* d_out, int out_size) {
    const float* x     = (const float*)d_in[0];
    const float* dww   = (const float*)d_in[1];
    const float* dwb   = (const float*)d_in[2];
    const float* bn1g  = (const float*)d_in[3];
    const float* bn1b  = (const float*)d_in[4];
    const float* pwinw = (const float*)d_in[5];
    const float* pwinb = (const float*)d_in[6];
    const float* gn1g  = (const float*)d_in[7];
    const float* gn1b  = (const float*)d_in[8];
    const float* qkvw  = (const float*)d_in[9];
    const float* qkvb  = (const float*)d_in[10];
    const float* outw  = (const float*)d_in[11];
    const float* outb  = (const float*)d_in[12];
    const float* gn2g  = (const float*)d_in[13];
    const float* gn2b  = (const float*)d_in[14];
    const float* ffn1w = (const float*)d_in[15];
    const float* ffn1b = (const float*)d_in[16];
    const float* ffn2w = (const float*)d_in[17];
    const float* ffn2b = (const float*)d_in[18];
    const float* gnfg  = (const float*)d_in[19];
    const float* gnfb  = (const float*)d_in[20];
    const float* projw = (const float*)d_in[21];
    const float* projb = (const float*)d_in[22];
    const float* bn2g  = (const float*)d_in[23];
    const float* bn2b  = (const float*)d_in[24];

    float *p_y, *p_p, *p_a, *p_h, *p_q, *p_s, *p_zs, *p_ctx, *p_wt;
    cudaGetSymbolAddress((void**)&p_y,   g_y);
    cudaGetSymbolAddress((void**)&p_p,   g_p);
    cudaGetSymbolAddress((void**)&p_a,   g_a);
    cudaGetSymbolAddress((void**)&p_h,   g_h);
    cudaGetSymbolAddress((void**)&p_q,   g_q);
    cudaGetSymbolAddress((void**)&p_s,   g_s);
    cudaGetSymbolAddress((void**)&p_zs,  g_zs);
    cudaGetSymbolAddress((void**)&p_ctx, g_ctx);
    cudaGetSymbolAddress((void**)&p_wt,  g_wt);

    // weight-transpose offsets
    const int OFF_PWIN = 0;
    const int OFF_V[2]   = {32768, 425984};
    const int OFF_OUT[2] = {98304, 491520};
    const int OFF_F1[2]  = {163840, 557056};
    const int OFF_F2[2]  = {294912, 688128};
    const int OFF_PROJ   = 819200;

    // Launch order arranged so the 6th launch (ncu -s 5 -c 1) is a big GEMM.
    zero_acc<<<1, 32>>>();                                               // 1
    tpose<<<128, 256>>>(pwinw, p_wt + OFF_PWIN, 256, 128);               // 2
    dw_silu<<<(NB * 128 * NPIX) / 256, 256>>>(x, dww, dwb, bn1g, bn1b, p_y); // 3
    tpose<<<256, 256>>>(qkvw + 257 * 256, p_wt + OFF_V[0], 256, 256);    // 4
    tpose<<<256, 256>>>(outw, p_wt + OFF_OUT[0], 256, 256);              // 5
    // 6: pw_in GEMM (profiled): p = W @ y + b, GN1 stats fused
    gemm_tc<EPI_BIAS, false, true><<<dim3(2, 512, NB), 256>>>(
        p_wt + OFF_PWIN, p_y, pwinb, p_p, 256, 128, nullptr, nullptr, nullptr, nullptr);

    tpose<<<512, 256>>>(ffn1w, p_wt + OFF_F1[0], 512, 256);
    tpose<<<512, 256>>>(ffn2w, p_wt + OFF_F2[0], 256, 512);
    tpose<<<256, 256>>>(qkvw + 513 * 256 + 257 * 256, p_wt + OFF_V[1], 256, 256);
    tpose<<<256, 256>>>(outw + 65536, p_wt + OFF_OUT[1], 256, 256);
    tpose<<<512, 256>>>(ffn1w + 131072, p_wt + OFF_F1[1], 512, 256);
    tpose<<<512, 256>>>(ffn2w + 131072, p_wt + OFF_F2[1], 256, 512);
    tpose<<<128, 256>>>(projw, p_wt + OFF_PROJ, 128, 256);

    for (int i = 0; i < 2; i++) {
        const float* qw = qkvw + (size_t)i * 513 * 256;
        const float* qb = qkvb + (size_t)i * 513;
        const float* g1 = gn1g + i * 256;
        const float* b1 = gn1b + i * 256;
        const float* g2 = gn2g + i * 256;
        const float* b2 = gn2b + i * 256;

        stats2<<<1, 32>>>();  // finalize GN1 stats

        // attention (linear form, GN folded)
        q_kernel<<<dim3(256, NB), 256>>>(p_p, qw, g1, p_q);
        softmax_k<<<dim3(64, NB), 256>>>(p_q, p_s);
        zs_k<<<dim3(256, NB), 256>>>(p_p, p_s, p_zs);
        ctx_k<<<dim3(256, NB), 64>>>(qw + 256, qb + 1, p_zs, p_ctx, g1, b1);

        // a = relu(Wv gn1(p) + bv) * ctx
        gemm_tc<EPI_RELU_CTX, true, false><<<dim3(2, 512, NB), 256>>>(
            p_wt + OFF_V[i], p_p, qb + 257, p_a, 256, 256, g1, b1, p_ctx, nullptr);
        // p += Wout a + bout ; GN2 stats fused
        gemm_tc<EPI_ADD, false, true><<<dim3(2, 512, NB), 256>>>(
            p_wt + OFF_OUT[i], p_a, outb + i * 256, p_p, 256, 256,
            nullptr, nullptr, nullptr, nullptr);

        stats2<<<1, 32>>>();  // finalize GN2 stats

        // h = silu(W1 gn2(p) + b1)
        gemm_tc<EPI_SILU, true, false><<<dim3(4, 512, NB), 256>>>(
            p_wt + OFF_F1[i], p_p, ffn1b + i * 512, p_h, 512, 256, g2, b2, nullptr, nullptr);
        // p += W2 h + b2 ; next-GN stats fused
        gemm_tc<EPI_ADD, false, true><<<dim3(2, 512, NB), 256>>>(
            p_wt + OFF_F2[i], p_h, ffn2b + i * 256, p_p, 256, 512,
            nullptr, nullptr, nullptr, nullptr);
    }

    stats2<<<1, 32>>>();  // finalize final-GN stats

    // out = bn2(proj(gnf(p)))
    gemm_tc<EPI_BN, true, false><<<dim3(1, 512, NB), 256>>>(
        p_wt + OFF_PROJ, p_p, projb, (float*)d_out, 128, 256, gnfg, gnfb, bn2g, bn2b);
}